// round 7
// baseline (speedup 1.0000x reference)
#include <cuda_runtime.h>
#include <cuda_fp16.h>
#include <cstdint>

// EdgeDecoder:
//   out[e] = relu(P[row]+Q[col]) . W2 + b2
// |W2| folded into PQ at epilogue; edge pass applies only signs (FFMA with
// +-1.0f from a precomputed table).
// Phase 1: tensor-core node GEMM (mma.m16n8k16 f16 -> f32) -> fp16 PQ table,
//          smem-staged coalesced STG.128 epilogue.
// Phase 2: edge gather + signed reduce, 8 lanes/edge, 2 edges/thread.

#define HIDDEN 64
#define NMAX   100000

__device__ __half    g_PQh[(size_t)NMAX * 128];  // [node][0:64]=P', [64:128]=Q'
__device__ int       g_idx_is64;
__device__ __align__(16) float g_sgnf[64];       // +-1.0f per column

// ---------------------------------------------------------------------------
__device__ __forceinline__ void mma16816(float* c,
                                         uint32_t a0, uint32_t a1,
                                         uint32_t a2, uint32_t a3,
                                         uint32_t b0, uint32_t b1) {
    asm volatile(
        "mma.sync.aligned.m16n8k16.row.col.f32.f16.f16.f32 "
        "{%0,%1,%2,%3}, {%4,%5,%6,%7}, {%8,%9}, {%0,%1,%2,%3};"
        : "+f"(c[0]), "+f"(c[1]), "+f"(c[2]), "+f"(c[3])
        : "r"(a0), "r"(a1), "r"(a2), "r"(a3), "r"(b0), "r"(b1));
}

// ---------------------------------------------------------------------------
// Node GEMM (tensor cores):
//   PQ[M,128] = fp16( (z[M,64] @ Wcat[64,128] + bias) * |W2| )
// Block: 128 rows x 128 cols, 8 warps; warp = 16 rows x 128 cols.
// Epilogue staged through smem (stride 136 halves -> conflict-free fragment
// writes, 16B-aligned rows) then coalesced uint4 stores.
// Block 0 also: sign table + int32/int64 index detection.
// ---------------------------------------------------------------------------
#define ZROW 72    // padded input row stride (halves)
#define SROW 136   // staging row stride (halves): 272 B, 16B-aligned

__global__ void __launch_bounds__(256, 2)
node_gemm_kernel(const float* __restrict__ z,
                 const float* __restrict__ W1,
                 const float* __restrict__ b1,
                 const float* __restrict__ W2,
                 const long long* __restrict__ ei,   // for idx-width detect
                 int n_check, int M) {
    __shared__ __half buf[128 * ZROW * 2];   // 36 KB: zh | wt, reused as stage
    __half* zh = buf;                        // z tile fp16, [r][k], stride ZROW
    __half* wt = buf + 128 * ZROW;           // W^T fp16,   [c][k], stride ZROW
    __shared__ float scale_s[128];
    __shared__ float bias_s[128];

    const int tid  = threadIdx.x;
    const int lane = tid & 31;
    const int warp = tid >> 5;
    const int row0 = blockIdx.x * 128;

    if (blockIdx.x == 0) {
        if (tid < 64)
            g_sgnf[tid] = (__ldg(W2 + tid) < 0.f) ? -1.f : 1.f;
        __shared__ int bad;
        if (tid == 0) bad = 0;
        __syncthreads();
        for (int i = tid; i < n_check; i += blockDim.x) {
            long long v = ei[i];
            if (v < 0 || v >= (long long)M) bad = 1;   // benign race
        }
        __syncthreads();
        if (tid == 0) g_idx_is64 = bad ? 0 : 1;
    }

    // ---- per-column scale & bias
    if (tid < 128) {
        int j = tid & 63;
        scale_s[tid] = fabsf(__ldg(W2 + j));
        bias_s[tid]  = (tid < 64) ? __ldg(b1 + tid) : 0.f;
    }

    // ---- W^T fp16 tile: wt[c][k], from W1 [128][64] row-major
    for (int i = tid; i < 128 * 64; i += 256) {
        int kp = i >> 6;
        int j  = i & 63;
        int c  = (kp < 64) ? j : (j + 64);
        int k  = (kp < 64) ? kp : (kp - 64);
        wt[c * ZROW + k] = __float2half(W1[i]);
    }

    // ---- z tile fp16: zh[r][k]
    for (int i = tid; i < 128 * 16; i += 256) {
        int r  = i >> 4;
        int c4 = i & 15;
        float4 v = make_float4(0.f, 0.f, 0.f, 0.f);
        if (row0 + r < M)
            v = *reinterpret_cast<const float4*>(z + (size_t)(row0 + r) * 64 + c4 * 4);
        __half2 h0 = __floats2half2_rn(v.x, v.y);
        __half2 h1 = __floats2half2_rn(v.z, v.w);
        *reinterpret_cast<__half2*>(&zh[r * ZROW + c4 * 4])     = h0;
        *reinterpret_cast<__half2*>(&zh[r * ZROW + c4 * 4 + 2]) = h1;
    }
    __syncthreads();

    // ---- mma mainloop
    const int g  = lane >> 2;
    const int tg = lane & 3;
    const int mrow = warp * 16;

    float acc[16][4];
#pragma unroll
    for (int t = 0; t < 16; t++)
#pragma unroll
        for (int i = 0; i < 4; i++) acc[t][i] = 0.f;

#pragma unroll
    for (int ks = 0; ks < 4; ks++) {
        const int kb = ks * 16 + 2 * tg;
        uint32_t a0 = *reinterpret_cast<const uint32_t*>(&zh[(mrow + g) * ZROW + kb]);
        uint32_t a1 = *reinterpret_cast<const uint32_t*>(&zh[(mrow + g + 8) * ZROW + kb]);
        uint32_t a2 = *reinterpret_cast<const uint32_t*>(&zh[(mrow + g) * ZROW + kb + 8]);
        uint32_t a3 = *reinterpret_cast<const uint32_t*>(&zh[(mrow + g + 8) * ZROW + kb + 8]);
#pragma unroll
        for (int t = 0; t < 16; t++) {
            uint32_t b0  = *reinterpret_cast<const uint32_t*>(&wt[(t * 8 + g) * ZROW + kb]);
            uint32_t b1r = *reinterpret_cast<const uint32_t*>(&wt[(t * 8 + g) * ZROW + kb + 8]);
            mma16816(acc[t], a0, a1, a2, a3, b0, b1r);
        }
    }

    // ---- epilogue: scale+bias, stage fp16 tile in smem, coalesced stores
    __syncthreads();                       // done reading zh/wt
    __half* stage = buf;                   // [128][SROW]
#pragma unroll
    for (int t = 0; t < 16; t++) {
        int n = t * 8 + 2 * tg;
        float s0 = scale_s[n], s1 = scale_s[n + 1];
        float bb0 = bias_s[n], bb1 = bias_s[n + 1];
        __half2 h0 = __floats2half2_rn((acc[t][0] + bb0) * s0,
                                       (acc[t][1] + bb1) * s1);
        __half2 h1 = __floats2half2_rn((acc[t][2] + bb0) * s0,
                                       (acc[t][3] + bb1) * s1);
        *reinterpret_cast<__half2*>(&stage[(mrow + g) * SROW + n])     = h0;
        *reinterpret_cast<__half2*>(&stage[(mrow + g + 8) * SROW + n]) = h1;
    }
    __syncthreads();

    // 128 rows x 128 halves = 2048 uint4, 8 per thread
#pragma unroll
    for (int i = 0; i < 8; i++) {
        int idx = tid + i * 256;
        int r   = idx >> 4;
        int c16 = idx & 15;
        if (row0 + r < M) {
            uint4 v = *reinterpret_cast<const uint4*>(&stage[r * SROW + c16 * 8]);
            *reinterpret_cast<uint4*>(&g_PQh[(size_t)(row0 + r) * 128 + c16 * 8]) = v;
        }
    }
}

// ---------------------------------------------------------------------------
// Edge pass: 8 lanes/edge, 2 edges/thread (e and e+half).
// Signs come from g_sgnf table (2 broadcast LDG.128, L1-resident).
// ---------------------------------------------------------------------------
__device__ __forceinline__ float edge_dot(const uint4& pv, const uint4& qv,
                                          const float* sgn) {
    const __half2* ph = reinterpret_cast<const __half2*>(&pv);
    const __half2* qh = reinterpret_cast<const __half2*>(&qv);
    const __half2 zero = __float2half2_rn(0.f);
    float s = 0.f;
#pragma unroll
    for (int i = 0; i < 4; i++) {
        __half2 h = __hmax2(__hadd2(ph[i], qh[i]), zero);
        float2 f = __half22float2(h);
        s = fmaf(f.x, sgn[2 * i], s);
        s = fmaf(f.y, sgn[2 * i + 1], s);
    }
    return s;
}

__global__ void __launch_bounds__(256)
edge_kernel(const void* __restrict__ ei_raw,
            const float* __restrict__ b2,
            float* __restrict__ out,
            int E, int half) {
    const int t = blockIdx.x * blockDim.x + threadIdx.x;
    const int e = t >> 3;
    if (e >= half) return;
    const int sub = t & 7;

    // per-lane sign constants from table (broadcast, L1-hit)
    const float4* sgt = reinterpret_cast<const float4*>(g_sgnf + sub * 8);
    const float4 sA = __ldg(sgt);
    const float4 sB = __ldg(sgt + 1);
    const float sgn[8] = {sA.x, sA.y, sA.z, sA.w, sB.x, sB.y, sB.z, sB.w};

    const int  e2   = e + half;
    const bool has2 = (e2 < E);
    const int  e2s  = has2 ? e2 : e;

    int r1, c1, r2, c2;
    if (g_idx_is64) {
        const long long* ei = reinterpret_cast<const long long*>(ei_raw);
        r1 = (int)ei[e];   c1 = (int)ei[(size_t)E + e];
        r2 = (int)ei[e2s]; c2 = (int)ei[(size_t)E + e2s];
    } else {
        const int* ei = reinterpret_cast<const int*>(ei_raw);
        r1 = ei[e];   c1 = ei[(size_t)E + e];
        r2 = ei[e2s]; c2 = ei[(size_t)E + e2s];
    }

    const uint4 p1 = __ldg(reinterpret_cast<const uint4*>(g_PQh + (size_t)r1 * 128 + sub * 8));
    const uint4 q1 = __ldg(reinterpret_cast<const uint4*>(g_PQh + (size_t)c1 * 128 + 64 + sub * 8));
    const uint4 p2 = __ldg(reinterpret_cast<const uint4*>(g_PQh + (size_t)r2 * 128 + sub * 8));
    const uint4 q2 = __ldg(reinterpret_cast<const uint4*>(g_PQh + (size_t)c2 * 128 + 64 + sub * 8));

    float s1 = edge_dot(p1, q1, sgn);
    float s2 = edge_dot(p2, q2, sgn);

    s1 += __shfl_down_sync(0xffffffffu, s1, 4, 8);
    s2 += __shfl_down_sync(0xffffffffu, s2, 4, 8);
    s1 += __shfl_down_sync(0xffffffffu, s1, 2, 8);
    s2 += __shfl_down_sync(0xffffffffu, s2, 2, 8);
    s1 += __shfl_down_sync(0xffffffffu, s1, 1, 8);
    s2 += __shfl_down_sync(0xffffffffu, s2, 1, 8);

    if (sub == 0) {
        const float bias = __ldg(b2);
        out[e] = s1 + bias;
        if (has2) out[e2] = s2 + bias;
    }
}

// ---------------------------------------------------------------------------
extern "C" void kernel_launch(void* const* d_in, const int* in_sizes, int n_in,
                              void* d_out, int out_size) {
    const float* z  = (const float*)d_in[0];   // [N, 64]
    const void*  ei = d_in[1];                 // [2, E] int64 or int32
    const float* W1 = (const float*)d_in[2];   // [128, 64]
    const float* b1 = (const float*)d_in[3];   // [64]
    const float* W2 = (const float*)d_in[4];   // [64, 1]
    const float* b2 = (const float*)d_in[5];   // [1]
    float* out = (float*)d_out;                // [E, 1]

    const int M = in_sizes[0] / HIDDEN;        // 100000 nodes
    const int E = in_sizes[1] / 2;             // 3200000 edges

    int n_check = E < 2048 ? E : 2048;
    int gemm_blocks = (M + 127) / 128;
    node_gemm_kernel<<<gemm_blocks, 256>>>(z, W1, b1, W2,
                                           (const long long*)ei, n_check, M);

    const int half = (E + 1) / 2;
    long long total_threads = (long long)half * 8;
    int edge_blocks = (int)((total_threads + 255) / 256);
    edge_kernel<<<edge_blocks, 256>>>(ei, b2, out, E, half);
}

// round 8
// speedup vs baseline: 1.1502x; 1.1502x over previous
#include <cuda_runtime.h>
#include <cuda_fp16.h>
#include <cstdint>

// EdgeDecoder:
//   out[e] = relu(P[row]+Q[col]) . W2 + b2
// |W2| folded into PQ at GEMM epilogue; edge pass applies signs via ALU
// unpack of a 64-bit mask (amortized over 4 edges/thread).
// Phase 1: tensor-core node GEMM (mma.m16n8k16), 4 row-tiles per block,
//          smem-staged coalesced stores.
// Phase 2: edge gather + signed reduce, 8 lanes/edge, 4 edges/thread.

#define HIDDEN 64
#define NMAX   100000

__device__ __half    g_PQh[(size_t)NMAX * 128];  // [node][0:64]=P', [64:128]=Q'
__device__ int       g_idx_is64;
__device__ uint32_t  g_sign[2];                  // bit j = 1 if W2[j] < 0

// ---------------------------------------------------------------------------
__device__ __forceinline__ void mma16816(float* c,
                                         uint32_t a0, uint32_t a1,
                                         uint32_t a2, uint32_t a3,
                                         uint32_t b0, uint32_t b1) {
    asm volatile(
        "mma.sync.aligned.m16n8k16.row.col.f32.f16.f16.f32 "
        "{%0,%1,%2,%3}, {%4,%5,%6,%7}, {%8,%9}, {%0,%1,%2,%3};"
        : "+f"(c[0]), "+f"(c[1]), "+f"(c[2]), "+f"(c[3])
        : "r"(a0), "r"(a1), "r"(a2), "r"(a3), "r"(b0), "r"(b1));
}

// ---------------------------------------------------------------------------
// Node GEMM: PQ[M,128] = fp16( (z[M,64] @ Wcat[64,128] + bias) * |W2| )
// 4 tiles of 128 rows per block; W^T fp16 prepared once per block.
// Epilogue staged through smem (64 rows/pass, stride 136 -> conflict-free).
// ---------------------------------------------------------------------------
#define ZROW 72    // input row stride (halves)
#define SROW 136   // staging row stride (halves)
#define TILES 4

__global__ void __launch_bounds__(256, 2)
node_gemm_kernel(const float* __restrict__ z,
                 const float* __restrict__ W1,
                 const float* __restrict__ b1,
                 const float* __restrict__ W2,
                 const long long* __restrict__ ei,   // for idx-width detect
                 int n_check, int M) {
    __shared__ __half zh[128 * ZROW];     // 18 KB; reused as 64-row stage
    __shared__ __half wt[128 * ZROW];     // 18 KB; W^T: wt[c][k]
    __shared__ float  scale_s[128];
    __shared__ float  bias_s[128];

    const int tid  = threadIdx.x;
    const int lane = tid & 31;
    const int warp = tid >> 5;

    if (blockIdx.x == 0) {
        if (tid < 64) {
            unsigned m = __ballot_sync(0xffffffffu, W2[tid] < 0.f);
            if ((tid & 31) == 0) g_sign[tid >> 5] = m;
        }
        __shared__ int bad;
        if (tid == 0) bad = 0;
        __syncthreads();
        for (int i = tid; i < n_check; i += blockDim.x) {
            long long v = ei[i];
            if (v < 0 || v >= (long long)M) bad = 1;   // benign race
        }
        __syncthreads();
        if (tid == 0) g_idx_is64 = bad ? 0 : 1;
    }

    // ---- per-column scale & bias (once per block)
    if (tid < 128) {
        int j = tid & 63;
        scale_s[tid] = fabsf(__ldg(W2 + j));
        bias_s[tid]  = (tid < 64) ? __ldg(b1 + tid) : 0.f;
    }

    // ---- W^T fp16 tile (once per block): wt[c][k] from W1 [128][64]
    for (int i = tid; i < 128 * 64; i += 256) {
        int kp = i >> 6;
        int j  = i & 63;
        int c  = (kp < 64) ? j : (j + 64);
        int k  = (kp < 64) ? kp : (kp - 64);
        wt[c * ZROW + k] = __float2half(W1[i]);
    }

    const int g  = lane >> 2;
    const int tg = lane & 3;
    const int mrow = warp * 16;

    for (int tt = 0; tt < TILES; tt++) {
        const int row0 = (blockIdx.x * TILES + tt) * 128;
        if (row0 >= M) break;

        __syncthreads();   // stage/W-prep done; safe to (re)fill zh

        // ---- z tile fp16: zh[r][k]
        for (int i = tid; i < 128 * 16; i += 256) {
            int r  = i >> 4;
            int c4 = i & 15;
            float4 v = make_float4(0.f, 0.f, 0.f, 0.f);
            if (row0 + r < M)
                v = *reinterpret_cast<const float4*>(z + (size_t)(row0 + r) * 64 + c4 * 4);
            __half2 h0 = __floats2half2_rn(v.x, v.y);
            __half2 h1 = __floats2half2_rn(v.z, v.w);
            *reinterpret_cast<__half2*>(&zh[r * ZROW + c4 * 4])     = h0;
            *reinterpret_cast<__half2*>(&zh[r * ZROW + c4 * 4 + 2]) = h1;
        }
        __syncthreads();

        // ---- mma mainloop
        float acc[16][4];
#pragma unroll
        for (int t = 0; t < 16; t++)
#pragma unroll
            for (int i = 0; i < 4; i++) acc[t][i] = 0.f;

#pragma unroll
        for (int ks = 0; ks < 4; ks++) {
            const int kb = ks * 16 + 2 * tg;
            uint32_t a0 = *reinterpret_cast<const uint32_t*>(&zh[(mrow + g) * ZROW + kb]);
            uint32_t a1 = *reinterpret_cast<const uint32_t*>(&zh[(mrow + g + 8) * ZROW + kb]);
            uint32_t a2 = *reinterpret_cast<const uint32_t*>(&zh[(mrow + g) * ZROW + kb + 8]);
            uint32_t a3 = *reinterpret_cast<const uint32_t*>(&zh[(mrow + g + 8) * ZROW + kb + 8]);
#pragma unroll
            for (int t = 0; t < 16; t++) {
                uint32_t b0  = *reinterpret_cast<const uint32_t*>(&wt[(t * 8 + g) * ZROW + kb]);
                uint32_t b1r = *reinterpret_cast<const uint32_t*>(&wt[(t * 8 + g) * ZROW + kb + 8]);
                mma16816(acc[t], a0, a1, a2, a3, b0, b1r);
            }
        }

        // ---- epilogue: two 64-row passes through zh-as-stage
        __half* stage = zh;
#pragma unroll
        for (int pass = 0; pass < 2; pass++) {
            __syncthreads();   // mma reads done / prior pass stores done
            if ((warp >> 2) == pass) {
                const int srow = mrow - pass * 64;   // 0..48
#pragma unroll
                for (int t = 0; t < 16; t++) {
                    int n = t * 8 + 2 * tg;
                    float s0 = scale_s[n], s1 = scale_s[n + 1];
                    float bb0 = bias_s[n], bb1 = bias_s[n + 1];
                    __half2 h0 = __floats2half2_rn((acc[t][0] + bb0) * s0,
                                                   (acc[t][1] + bb1) * s1);
                    __half2 h1 = __floats2half2_rn((acc[t][2] + bb0) * s0,
                                                   (acc[t][3] + bb1) * s1);
                    *reinterpret_cast<__half2*>(&stage[(srow + g) * SROW + n])     = h0;
                    *reinterpret_cast<__half2*>(&stage[(srow + g + 8) * SROW + n]) = h1;
                }
            }
            __syncthreads();
            // store 64 rows x 128 halves = 1024 uint4, 4 per thread
#pragma unroll
            for (int i = 0; i < 4; i++) {
                int idx = tid + i * 256;
                int r   = idx >> 4;
                int c16 = idx & 15;
                int grow = row0 + pass * 64 + r;
                if (grow < M) {
                    uint4 v = *reinterpret_cast<const uint4*>(&stage[r * SROW + c16 * 8]);
                    *reinterpret_cast<uint4*>(&g_PQh[(size_t)grow * 128 + c16 * 8]) = v;
                }
            }
        }
    }
}

// ---------------------------------------------------------------------------
// Edge pass: 8 lanes/edge, 4 edges/thread (e, e+q, e+2q, e+3q).
// Sign constants unpacked once per thread (ALU), amortized over 4 edges.
// ---------------------------------------------------------------------------
__device__ __forceinline__ float edge_dot(const uint4& pv, const uint4& qv,
                                          const float* sgn) {
    const __half2* ph = reinterpret_cast<const __half2*>(&pv);
    const __half2* qh = reinterpret_cast<const __half2*>(&qv);
    const __half2 zero = __float2half2_rn(0.f);
    float s = 0.f;
#pragma unroll
    for (int i = 0; i < 4; i++) {
        __half2 h = __hmax2(__hadd2(ph[i], qh[i]), zero);
        float2 f = __half22float2(h);
        s = fmaf(f.x, sgn[2 * i], s);
        s = fmaf(f.y, sgn[2 * i + 1], s);
    }
    return s;
}

__global__ void __launch_bounds__(256)
edge_kernel(const void* __restrict__ ei_raw,
            const float* __restrict__ b2,
            float* __restrict__ out,
            int E, int quarter) {
    const int t = blockIdx.x * blockDim.x + threadIdx.x;
    const int e1 = t >> 3;
    if (e1 >= quarter) return;
    const int sub = t & 7;

    const uint32_t bits = g_sign[sub >> 2];
    const uint32_t b8 = (bits >> ((sub & 3) * 8)) & 0xFFu;
    float sgn[8];
#pragma unroll
    for (int k = 0; k < 8; k++)
        sgn[k] = ((b8 >> k) & 1u) ? -1.f : 1.f;

    const int e2 = e1 + quarter;
    const int e3 = e1 + 2 * quarter;
    const int e4 = e1 + 3 * quarter;
    const bool h2 = (e2 < E), h3 = (e3 < E), h4 = (e4 < E);
    const int e2s = h2 ? e2 : e1;
    const int e3s = h3 ? e3 : e1;
    const int e4s = h4 ? e4 : e1;

    const bool is64 = (g_idx_is64 != 0);
    const long long* ei64 = reinterpret_cast<const long long*>(ei_raw);
    const int*       ei32 = reinterpret_cast<const int*>(ei_raw);

    float s1, s2, s3, s4;
    {   // pair 1: edges e1, e2
        int r1, c1, r2, c2;
        if (is64) {
            r1 = (int)ei64[e1];  c1 = (int)ei64[(size_t)E + e1];
            r2 = (int)ei64[e2s]; c2 = (int)ei64[(size_t)E + e2s];
        } else {
            r1 = ei32[e1];  c1 = ei32[(size_t)E + e1];
            r2 = ei32[e2s]; c2 = ei32[(size_t)E + e2s];
        }
        const uint4 p1 = __ldg(reinterpret_cast<const uint4*>(g_PQh + (size_t)r1 * 128 + sub * 8));
        const uint4 q1 = __ldg(reinterpret_cast<const uint4*>(g_PQh + (size_t)c1 * 128 + 64 + sub * 8));
        const uint4 p2 = __ldg(reinterpret_cast<const uint4*>(g_PQh + (size_t)r2 * 128 + sub * 8));
        const uint4 q2 = __ldg(reinterpret_cast<const uint4*>(g_PQh + (size_t)c2 * 128 + 64 + sub * 8));
        s1 = edge_dot(p1, q1, sgn);
        s2 = edge_dot(p2, q2, sgn);
    }
    {   // pair 2: edges e3, e4
        int r3, c3, r4, c4;
        if (is64) {
            r3 = (int)ei64[e3s]; c3 = (int)ei64[(size_t)E + e3s];
            r4 = (int)ei64[e4s]; c4 = (int)ei64[(size_t)E + e4s];
        } else {
            r3 = ei32[e3s]; c3 = ei32[(size_t)E + e3s];
            r4 = ei32[e4s]; c4 = ei32[(size_t)E + e4s];
        }
        const uint4 p3 = __ldg(reinterpret_cast<const uint4*>(g_PQh + (size_t)r3 * 128 + sub * 8));
        const uint4 q3 = __ldg(reinterpret_cast<const uint4*>(g_PQh + (size_t)c3 * 128 + 64 + sub * 8));
        const uint4 p4 = __ldg(reinterpret_cast<const uint4*>(g_PQh + (size_t)r4 * 128 + sub * 8));
        const uint4 q4 = __ldg(reinterpret_cast<const uint4*>(g_PQh + (size_t)c4 * 128 + 64 + sub * 8));
        s3 = edge_dot(p3, q3, sgn);
        s4 = edge_dot(p4, q4, sgn);
    }

    s1 += __shfl_down_sync(0xffffffffu, s1, 4, 8);
    s2 += __shfl_down_sync(0xffffffffu, s2, 4, 8);
    s3 += __shfl_down_sync(0xffffffffu, s3, 4, 8);
    s4 += __shfl_down_sync(0xffffffffu, s4, 4, 8);
    s1 += __shfl_down_sync(0xffffffffu, s1, 2, 8);
    s2 += __shfl_down_sync(0xffffffffu, s2, 2, 8);
    s3 += __shfl_down_sync(0xffffffffu, s3, 2, 8);
    s4 += __shfl_down_sync(0xffffffffu, s4, 2, 8);
    s1 += __shfl_down_sync(0xffffffffu, s1, 1, 8);
    s2 += __shfl_down_sync(0xffffffffu, s2, 1, 8);
    s3 += __shfl_down_sync(0xffffffffu, s3, 1, 8);
    s4 += __shfl_down_sync(0xffffffffu, s4, 1, 8);

    if (sub == 0) {
        const float bias = __ldg(b2);
        out[e1] = s1 + bias;
        if (h2) out[e2] = s2 + bias;
        if (h3) out[e3] = s3 + bias;
        if (h4) out[e4] = s4 + bias;
    }
}

// ---------------------------------------------------------------------------
extern "C" void kernel_launch(void* const* d_in, const int* in_sizes, int n_in,
                              void* d_out, int out_size) {
    const float* z  = (const float*)d_in[0];   // [N, 64]
    const void*  ei = d_in[1];                 // [2, E] int64 or int32
    const float* W1 = (const float*)d_in[2];   // [128, 64]
    const float* b1 = (const float*)d_in[3];   // [64]
    const float* W2 = (const float*)d_in[4];   // [64, 1]
    const float* b2 = (const float*)d_in[5];   // [1]
    float* out = (float*)d_out;                // [E, 1]

    const int M = in_sizes[0] / HIDDEN;        // 100000 nodes
    const int E = in_sizes[1] / 2;             // 3200000 edges

    int n_check = E < 2048 ? E : 2048;
    int gemm_blocks = (M + 128 * TILES - 1) / (128 * TILES);
    node_gemm_kernel<<<gemm_blocks, 256>>>(z, W1, b1, W2,
                                           (const long long*)ei, n_check, M);

    const int quarter = (E + 3) / 4;
    long long total_threads = (long long)quarter * 8;
    int edge_blocks = (int)((total_threads + 255) / 256);
    edge_kernel<<<edge_blocks, 256>>>(ei, b2, out, E, quarter);
}

// round 9
// speedup vs baseline: 1.1564x; 1.0054x over previous
#include <cuda_runtime.h>
#include <cuda_fp16.h>
#include <cstdint>

// EdgeDecoder:
//   out[e] = relu(P[row]+Q[col]) . W2 + b2
// |W2| folded into PQ at GEMM epilogue; edge pass applies signs by XORing
// the fp16 sign bit post-relu (4 packed masks/thread, amortized 4 edges).
// Phase 1: tensor-core node GEMM (mma.m16n8k16), 4 row-tiles per block.
// Phase 2: edge gather + signed reduce, 8 lanes/edge, 4 edges/thread,
//          forced <=32 regs for full occupancy.

#define HIDDEN 64
#define NMAX   100000

__device__ __half    g_PQh[(size_t)NMAX * 128];  // [node][0:64]=P', [64:128]=Q'
__device__ int       g_idx_is64;
__device__ uint32_t  g_sign[2];                  // bit j = 1 if W2[j] < 0

// ---------------------------------------------------------------------------
__device__ __forceinline__ void mma16816(float* c,
                                         uint32_t a0, uint32_t a1,
                                         uint32_t a2, uint32_t a3,
                                         uint32_t b0, uint32_t b1) {
    asm volatile(
        "mma.sync.aligned.m16n8k16.row.col.f32.f16.f16.f32 "
        "{%0,%1,%2,%3}, {%4,%5,%6,%7}, {%8,%9}, {%0,%1,%2,%3};"
        : "+f"(c[0]), "+f"(c[1]), "+f"(c[2]), "+f"(c[3])
        : "r"(a0), "r"(a1), "r"(a2), "r"(a3), "r"(b0), "r"(b1));
}

// ---------------------------------------------------------------------------
// Node GEMM: PQ[M,128] = fp16( (z[M,64] @ Wcat[64,128] + bias) * |W2| )
// 4 tiles of 128 rows per block; W^T fp16 prepared once per block.
// ---------------------------------------------------------------------------
#define ZROW 72
#define SROW 136
#define TILES 4

__global__ void __launch_bounds__(256, 2)
node_gemm_kernel(const float* __restrict__ z,
                 const float* __restrict__ W1,
                 const float* __restrict__ b1,
                 const float* __restrict__ W2,
                 const long long* __restrict__ ei,
                 int n_check, int M) {
    __shared__ __half zh[128 * ZROW];     // 18 KB; reused as 64-row stage
    __shared__ __half wt[128 * ZROW];     // 18 KB; W^T: wt[c][k]
    __shared__ float  scale_s[128];
    __shared__ float  bias_s[128];

    const int tid  = threadIdx.x;
    const int lane = tid & 31;
    const int warp = tid >> 5;

    if (blockIdx.x == 0) {
        if (tid < 64) {
            unsigned m = __ballot_sync(0xffffffffu, W2[tid] < 0.f);
            if ((tid & 31) == 0) g_sign[tid >> 5] = m;
        }
        __shared__ int bad;
        if (tid == 0) bad = 0;
        __syncthreads();
        for (int i = tid; i < n_check; i += blockDim.x) {
            long long v = ei[i];
            if (v < 0 || v >= (long long)M) bad = 1;   // benign race
        }
        __syncthreads();
        if (tid == 0) g_idx_is64 = bad ? 0 : 1;
    }

    if (tid < 128) {
        int j = tid & 63;
        scale_s[tid] = fabsf(__ldg(W2 + j));
        bias_s[tid]  = (tid < 64) ? __ldg(b1 + tid) : 0.f;
    }

    for (int i = tid; i < 128 * 64; i += 256) {
        int kp = i >> 6;
        int j  = i & 63;
        int c  = (kp < 64) ? j : (j + 64);
        int k  = (kp < 64) ? kp : (kp - 64);
        wt[c * ZROW + k] = __float2half(W1[i]);
    }

    const int g  = lane >> 2;
    const int tg = lane & 3;
    const int mrow = warp * 16;

    for (int tt = 0; tt < TILES; tt++) {
        const int row0 = (blockIdx.x * TILES + tt) * 128;
        if (row0 >= M) break;

        __syncthreads();

        for (int i = tid; i < 128 * 16; i += 256) {
            int r  = i >> 4;
            int c4 = i & 15;
            float4 v = make_float4(0.f, 0.f, 0.f, 0.f);
            if (row0 + r < M)
                v = *reinterpret_cast<const float4*>(z + (size_t)(row0 + r) * 64 + c4 * 4);
            __half2 h0 = __floats2half2_rn(v.x, v.y);
            __half2 h1 = __floats2half2_rn(v.z, v.w);
            *reinterpret_cast<__half2*>(&zh[r * ZROW + c4 * 4])     = h0;
            *reinterpret_cast<__half2*>(&zh[r * ZROW + c4 * 4 + 2]) = h1;
        }
        __syncthreads();

        float acc[16][4];
#pragma unroll
        for (int t = 0; t < 16; t++)
#pragma unroll
            for (int i = 0; i < 4; i++) acc[t][i] = 0.f;

#pragma unroll
        for (int ks = 0; ks < 4; ks++) {
            const int kb = ks * 16 + 2 * tg;
            uint32_t a0 = *reinterpret_cast<const uint32_t*>(&zh[(mrow + g) * ZROW + kb]);
            uint32_t a1 = *reinterpret_cast<const uint32_t*>(&zh[(mrow + g + 8) * ZROW + kb]);
            uint32_t a2 = *reinterpret_cast<const uint32_t*>(&zh[(mrow + g) * ZROW + kb + 8]);
            uint32_t a3 = *reinterpret_cast<const uint32_t*>(&zh[(mrow + g + 8) * ZROW + kb + 8]);
#pragma unroll
            for (int t = 0; t < 16; t++) {
                uint32_t b0  = *reinterpret_cast<const uint32_t*>(&wt[(t * 8 + g) * ZROW + kb]);
                uint32_t b1r = *reinterpret_cast<const uint32_t*>(&wt[(t * 8 + g) * ZROW + kb + 8]);
                mma16816(acc[t], a0, a1, a2, a3, b0, b1r);
            }
        }

        __half* stage = zh;
#pragma unroll
        for (int pass = 0; pass < 2; pass++) {
            __syncthreads();
            if ((warp >> 2) == pass) {
                const int srow = mrow - pass * 64;
#pragma unroll
                for (int t = 0; t < 16; t++) {
                    int n = t * 8 + 2 * tg;
                    float s0 = scale_s[n], s1 = scale_s[n + 1];
                    float bb0 = bias_s[n], bb1 = bias_s[n + 1];
                    __half2 h0 = __floats2half2_rn((acc[t][0] + bb0) * s0,
                                                   (acc[t][1] + bb1) * s1);
                    __half2 h1 = __floats2half2_rn((acc[t][2] + bb0) * s0,
                                                   (acc[t][3] + bb1) * s1);
                    *reinterpret_cast<__half2*>(&stage[(srow + g) * SROW + n])     = h0;
                    *reinterpret_cast<__half2*>(&stage[(srow + g + 8) * SROW + n]) = h1;
                }
            }
            __syncthreads();
#pragma unroll
            for (int i = 0; i < 4; i++) {
                int idx = tid + i * 256;
                int r   = idx >> 4;
                int c16 = idx & 15;
                int grow = row0 + pass * 64 + r;
                if (grow < M) {
                    uint4 v = *reinterpret_cast<const uint4*>(&stage[r * SROW + c16 * 8]);
                    *reinterpret_cast<uint4*>(&g_PQh[(size_t)grow * 128 + c16 * 8]) = v;
                }
            }
        }
    }
}

// ---------------------------------------------------------------------------
// Edge pass: 8 lanes/edge, 4 edges/thread.
// Signs applied as fp16 sign-bit XOR after relu (4 packed masks/thread).
// ---------------------------------------------------------------------------
__device__ __forceinline__ float edge_dot(const uint4& pv, const uint4& qv,
                                          const uint32_t* msk) {
    const __half2* ph = reinterpret_cast<const __half2*>(&pv);
    const __half2* qh = reinterpret_cast<const __half2*>(&qv);
    const __half2 zero = __float2half2_rn(0.f);
    float s = 0.f;
#pragma unroll
    for (int i = 0; i < 4; i++) {
        __half2 h = __hmax2(__hadd2(ph[i], qh[i]), zero);
        uint32_t u = *reinterpret_cast<uint32_t*>(&h) ^ msk[i];
        __half2 hs = *reinterpret_cast<__half2*>(&u);
        float2 f = __half22float2(hs);
        s += f.x;
        s += f.y;
    }
    return s;
}

__global__ void __launch_bounds__(256, 8)
edge_kernel(const void* __restrict__ ei_raw,
            const float* __restrict__ b2,
            float* __restrict__ out,
            int E, int quarter) {
    const int t = blockIdx.x * blockDim.x + threadIdx.x;
    const int e1 = t >> 3;
    if (e1 >= quarter) return;
    const int sub = t & 7;

    // 4 packed sign masks: mask[i] flips halves (2i, 2i+1) of this lane
    const uint32_t bits = g_sign[sub >> 2];
    const uint32_t b8 = (bits >> ((sub & 3) * 8)) & 0xFFu;
    uint32_t msk[4];
#pragma unroll
    for (int i = 0; i < 4; i++)
        msk[i] = (((b8 >> (2 * i)) & 1u) << 15) |
                 (((b8 >> (2 * i + 1)) & 1u) << 31);

    const int e2 = e1 + quarter;
    const int e3 = e1 + 2 * quarter;
    const int e4 = e1 + 3 * quarter;
    const bool h2 = (e2 < E), h3 = (e3 < E), h4 = (e4 < E);
    const int e2s = h2 ? e2 : e1;
    const int e3s = h3 ? e3 : e1;
    const int e4s = h4 ? e4 : e1;

    const bool is64 = (g_idx_is64 != 0);
    const long long* ei64 = reinterpret_cast<const long long*>(ei_raw);
    const int*       ei32 = reinterpret_cast<const int*>(ei_raw);

    float s1, s2, s3, s4;
    {
        int r1, c1, r2, c2;
        if (is64) {
            r1 = (int)ei64[e1];  c1 = (int)ei64[(size_t)E + e1];
            r2 = (int)ei64[e2s]; c2 = (int)ei64[(size_t)E + e2s];
        } else {
            r1 = ei32[e1];  c1 = ei32[(size_t)E + e1];
            r2 = ei32[e2s]; c2 = ei32[(size_t)E + e2s];
        }
        const uint4 p1 = __ldg(reinterpret_cast<const uint4*>(g_PQh + (size_t)r1 * 128 + sub * 8));
        const uint4 q1 = __ldg(reinterpret_cast<const uint4*>(g_PQh + (size_t)c1 * 128 + 64 + sub * 8));
        const uint4 p2 = __ldg(reinterpret_cast<const uint4*>(g_PQh + (size_t)r2 * 128 + sub * 8));
        const uint4 q2 = __ldg(reinterpret_cast<const uint4*>(g_PQh + (size_t)c2 * 128 + 64 + sub * 8));
        s1 = edge_dot(p1, q1, msk);
        s2 = edge_dot(p2, q2, msk);
    }
    {
        int r3, c3, r4, c4;
        if (is64) {
            r3 = (int)ei64[e3s]; c3 = (int)ei64[(size_t)E + e3s];
            r4 = (int)ei64[e4s]; c4 = (int)ei64[(size_t)E + e4s];
        } else {
            r3 = ei32[e3s]; c3 = ei32[(size_t)E + e3s];
            r4 = ei32[e4s]; c4 = ei32[(size_t)E + e4s];
        }
        const uint4 p3 = __ldg(reinterpret_cast<const uint4*>(g_PQh + (size_t)r3 * 128 + sub * 8));
        const uint4 q3 = __ldg(reinterpret_cast<const uint4*>(g_PQh + (size_t)c3 * 128 + 64 + sub * 8));
        const uint4 p4 = __ldg(reinterpret_cast<const uint4*>(g_PQh + (size_t)r4 * 128 + sub * 8));
        const uint4 q4 = __ldg(reinterpret_cast<const uint4*>(g_PQh + (size_t)c4 * 128 + 64 + sub * 8));
        s3 = edge_dot(p3, q3, msk);
        s4 = edge_dot(p4, q4, msk);
    }

    s1 += __shfl_down_sync(0xffffffffu, s1, 4, 8);
    s2 += __shfl_down_sync(0xffffffffu, s2, 4, 8);
    s3 += __shfl_down_sync(0xffffffffu, s3, 4, 8);
    s4 += __shfl_down_sync(0xffffffffu, s4, 4, 8);
    s1 += __shfl_down_sync(0xffffffffu, s1, 2, 8);
    s2 += __shfl_down_sync(0xffffffffu, s2, 2, 8);
    s3 += __shfl_down_sync(0xffffffffu, s3, 2, 8);
    s4 += __shfl_down_sync(0xffffffffu, s4, 2, 8);
    s1 += __shfl_down_sync(0xffffffffu, s1, 1, 8);
    s2 += __shfl_down_sync(0xffffffffu, s2, 1, 8);
    s3 += __shfl_down_sync(0xffffffffu, s3, 1, 8);
    s4 += __shfl_down_sync(0xffffffffu, s4, 1, 8);

    if (sub == 0) {
        const float bias = __ldg(b2);
        out[e1] = s1 + bias;
        if (h2) out[e2] = s2 + bias;
        if (h3) out[e3] = s3 + bias;
        if (h4) out[e4] = s4 + bias;
    }
}

// ---------------------------------------------------------------------------
extern "C" void kernel_launch(void* const* d_in, const int* in_sizes, int n_in,
                              void* d_out, int out_size) {
    const float* z  = (const float*)d_in[0];   // [N, 64]
    const void*  ei = d_in[1];                 // [2, E] int64 or int32
    const float* W1 = (const float*)d_in[2];   // [128, 64]
    const float* b1 = (const float*)d_in[3];   // [64]
    const float* W2 = (const float*)d_in[4];   // [64, 1]
    const float* b2 = (const float*)d_in[5];   // [1]
    float* out = (float*)d_out;                // [E, 1]

    const int M = in_sizes[0] / HIDDEN;        // 100000 nodes
    const int E = in_sizes[1] / 2;             // 3200000 edges

    int n_check = E < 2048 ? E : 2048;
    int gemm_blocks = (M + 128 * TILES - 1) / (128 * TILES);
    node_gemm_kernel<<<gemm_blocks, 256>>>(z, W1, b1, W2,
                                           (const long long*)ei, n_check, M);

    const int quarter = (E + 3) / 4;
    long long total_threads = (long long)quarter * 8;
    int edge_blocks = (int)((total_threads + 255) / 256);
    edge_kernel<<<edge_blocks, 256>>>(ei, b2, out, E, quarter);
}

// round 10
// speedup vs baseline: 1.2489x; 1.0800x over previous
#include <cuda_runtime.h>
#include <cuda_fp16.h>
#include <cstdint>

// EdgeDecoder:
//   out[e] = relu(P[row]+Q[col]) . W2 + b2
// |W2| folded into PQ at GEMM epilogue; edge pass applies signs by XORing
// the fp16 sign bit post-relu, then a one-level hadd2 tree before fp32.
// Phase 1: tensor-core node GEMM (mma.m16n8k16), 4 row-tiles per block.
// Phase 2: edge pass, 8 lanes/edge, 4 CONSECUTIVE edges per lane-slot:
//          vector int4/longlong2 index loads, float4 output store.

#define HIDDEN 64
#define NMAX   100000

__device__ __half    g_PQh[(size_t)NMAX * 128];  // [node][0:64]=P', [64:128]=Q'
__device__ int       g_idx_is64;
__device__ uint32_t  g_sign[2];                  // bit j = 1 if W2[j] < 0

// ---------------------------------------------------------------------------
__device__ __forceinline__ void mma16816(float* c,
                                         uint32_t a0, uint32_t a1,
                                         uint32_t a2, uint32_t a3,
                                         uint32_t b0, uint32_t b1) {
    asm volatile(
        "mma.sync.aligned.m16n8k16.row.col.f32.f16.f16.f32 "
        "{%0,%1,%2,%3}, {%4,%5,%6,%7}, {%8,%9}, {%0,%1,%2,%3};"
        : "+f"(c[0]), "+f"(c[1]), "+f"(c[2]), "+f"(c[3])
        : "r"(a0), "r"(a1), "r"(a2), "r"(a3), "r"(b0), "r"(b1));
}

// ---------------------------------------------------------------------------
// Node GEMM: PQ[M,128] = fp16( (z[M,64] @ Wcat[64,128] + bias) * |W2| )
// 4 tiles of 128 rows per block; W^T fp16 prepared once per block.
// ---------------------------------------------------------------------------
#define ZROW 72
#define SROW 136
#define TILES 4

__global__ void __launch_bounds__(256, 2)
node_gemm_kernel(const float* __restrict__ z,
                 const float* __restrict__ W1,
                 const float* __restrict__ b1,
                 const float* __restrict__ W2,
                 const long long* __restrict__ ei,
                 int n_check, int M) {
    __shared__ __half zh[128 * ZROW];     // 18 KB; reused as 64-row stage
    __shared__ __half wt[128 * ZROW];     // 18 KB; W^T: wt[c][k]
    __shared__ float  scale_s[128];
    __shared__ float  bias_s[128];

    const int tid  = threadIdx.x;
    const int lane = tid & 31;
    const int warp = tid >> 5;

    if (blockIdx.x == 0) {
        if (tid < 64) {
            unsigned m = __ballot_sync(0xffffffffu, W2[tid] < 0.f);
            if ((tid & 31) == 0) g_sign[tid >> 5] = m;
        }
        __shared__ int bad;
        if (tid == 0) bad = 0;
        __syncthreads();
        for (int i = tid; i < n_check; i += blockDim.x) {
            long long v = ei[i];
            if (v < 0 || v >= (long long)M) bad = 1;   // benign race
        }
        __syncthreads();
        if (tid == 0) g_idx_is64 = bad ? 0 : 1;
    }

    if (tid < 128) {
        int j = tid & 63;
        scale_s[tid] = fabsf(__ldg(W2 + j));
        bias_s[tid]  = (tid < 64) ? __ldg(b1 + tid) : 0.f;
    }

    for (int i = tid; i < 128 * 64; i += 256) {
        int kp = i >> 6;
        int j  = i & 63;
        int c  = (kp < 64) ? j : (j + 64);
        int k  = (kp < 64) ? kp : (kp - 64);
        wt[c * ZROW + k] = __float2half(W1[i]);
    }

    const int g  = lane >> 2;
    const int tg = lane & 3;
    const int mrow = warp * 16;

    for (int tt = 0; tt < TILES; tt++) {
        const int row0 = (blockIdx.x * TILES + tt) * 128;
        if (row0 >= M) break;

        __syncthreads();

        for (int i = tid; i < 128 * 16; i += 256) {
            int r  = i >> 4;
            int c4 = i & 15;
            float4 v = make_float4(0.f, 0.f, 0.f, 0.f);
            if (row0 + r < M)
                v = *reinterpret_cast<const float4*>(z + (size_t)(row0 + r) * 64 + c4 * 4);
            __half2 h0 = __floats2half2_rn(v.x, v.y);
            __half2 h1 = __floats2half2_rn(v.z, v.w);
            *reinterpret_cast<__half2*>(&zh[r * ZROW + c4 * 4])     = h0;
            *reinterpret_cast<__half2*>(&zh[r * ZROW + c4 * 4 + 2]) = h1;
        }
        __syncthreads();

        float acc[16][4];
#pragma unroll
        for (int t = 0; t < 16; t++)
#pragma unroll
            for (int i = 0; i < 4; i++) acc[t][i] = 0.f;

#pragma unroll
        for (int ks = 0; ks < 4; ks++) {
            const int kb = ks * 16 + 2 * tg;
            uint32_t a0 = *reinterpret_cast<const uint32_t*>(&zh[(mrow + g) * ZROW + kb]);
            uint32_t a1 = *reinterpret_cast<const uint32_t*>(&zh[(mrow + g + 8) * ZROW + kb]);
            uint32_t a2 = *reinterpret_cast<const uint32_t*>(&zh[(mrow + g) * ZROW + kb + 8]);
            uint32_t a3 = *reinterpret_cast<const uint32_t*>(&zh[(mrow + g + 8) * ZROW + kb + 8]);
#pragma unroll
            for (int t = 0; t < 16; t++) {
                uint32_t b0  = *reinterpret_cast<const uint32_t*>(&wt[(t * 8 + g) * ZROW + kb]);
                uint32_t b1r = *reinterpret_cast<const uint32_t*>(&wt[(t * 8 + g) * ZROW + kb + 8]);
                mma16816(acc[t], a0, a1, a2, a3, b0, b1r);
            }
        }

        __half* stage = zh;
#pragma unroll
        for (int pass = 0; pass < 2; pass++) {
            __syncthreads();
            if ((warp >> 2) == pass) {
                const int srow = mrow - pass * 64;
#pragma unroll
                for (int t = 0; t < 16; t++) {
                    int n = t * 8 + 2 * tg;
                    float s0 = scale_s[n], s1 = scale_s[n + 1];
                    float bb0 = bias_s[n], bb1 = bias_s[n + 1];
                    __half2 h0 = __floats2half2_rn((acc[t][0] + bb0) * s0,
                                                   (acc[t][1] + bb1) * s1);
                    __half2 h1 = __floats2half2_rn((acc[t][2] + bb0) * s0,
                                                   (acc[t][3] + bb1) * s1);
                    *reinterpret_cast<__half2*>(&stage[(srow + g) * SROW + n])     = h0;
                    *reinterpret_cast<__half2*>(&stage[(srow + g + 8) * SROW + n]) = h1;
                }
            }
            __syncthreads();
#pragma unroll
            for (int i = 0; i < 4; i++) {
                int idx = tid + i * 256;
                int r   = idx >> 4;
                int c16 = idx & 15;
                int grow = row0 + pass * 64 + r;
                if (grow < M) {
                    uint4 v = *reinterpret_cast<const uint4*>(&stage[r * SROW + c16 * 8]);
                    *reinterpret_cast<uint4*>(&g_PQh[(size_t)grow * 128 + c16 * 8]) = v;
                }
            }
        }
    }
}

// ---------------------------------------------------------------------------
// Edge pass: 8 lanes/edge, 4 consecutive edges per slot.
// ---------------------------------------------------------------------------
__device__ __forceinline__ float edge_dot(const uint4& pv, const uint4& qv,
                                          const uint32_t* msk) {
    const __half2* ph = reinterpret_cast<const __half2*>(&pv);
    const __half2* qh = reinterpret_cast<const __half2*>(&qv);
    const __half2 zero = __float2half2_rn(0.f);
    __half2 hs[4];
#pragma unroll
    for (int i = 0; i < 4; i++) {
        __half2 h = __hmax2(__hadd2(ph[i], qh[i]), zero);
        uint32_t u = *reinterpret_cast<uint32_t*>(&h) ^ msk[i];
        hs[i] = *reinterpret_cast<__half2*>(&u);
    }
    __half2 t0 = __hadd2(hs[0], hs[1]);     // one fp16 add level
    __half2 t1 = __hadd2(hs[2], hs[3]);
    float2 f0 = __half22float2(t0);
    float2 f1 = __half22float2(t1);
    return (f0.x + f0.y) + (f1.x + f1.y);
}

__global__ void __launch_bounds__(256)
edge_kernel(const void* __restrict__ ei_raw,
            const float* __restrict__ b2,
            float* __restrict__ out,
            int E, int nslots) {
    const int t = blockIdx.x * blockDim.x + threadIdx.x;
    const int slot = t >> 3;
    if (slot >= nslots) return;
    const int sub = t & 7;
    const int e0 = slot * 4;

    const uint32_t bits = g_sign[sub >> 2];
    const uint32_t b8 = (bits >> ((sub & 3) * 8)) & 0xFFu;
    uint32_t msk[4];
#pragma unroll
    for (int i = 0; i < 4; i++)
        msk[i] = (((b8 >> (2 * i)) & 1u) << 15) |
                 (((b8 >> (2 * i + 1)) & 1u) << 31);

    const bool is64 = (g_idx_is64 != 0);
    const bool full = ((E & 3) == 0);   // vector path (always true here)

    int r[4], c[4];
    if (full) {
        if (is64) {
            const longlong2* pr = reinterpret_cast<const longlong2*>(
                (const long long*)ei_raw + e0);
            longlong2 a = __ldg(pr), b = __ldg(pr + 1);
            r[0] = (int)a.x; r[1] = (int)a.y; r[2] = (int)b.x; r[3] = (int)b.y;
            const longlong2* pc = reinterpret_cast<const longlong2*>(
                (const long long*)ei_raw + (size_t)E + e0);
            longlong2 d = __ldg(pc), f = __ldg(pc + 1);
            c[0] = (int)d.x; c[1] = (int)d.y; c[2] = (int)f.x; c[3] = (int)f.y;
        } else {
            int4 a = __ldg(reinterpret_cast<const int4*>((const int*)ei_raw + e0));
            r[0] = a.x; r[1] = a.y; r[2] = a.z; r[3] = a.w;
            int4 d = __ldg(reinterpret_cast<const int4*>(
                (const int*)ei_raw + (size_t)E + e0));
            c[0] = d.x; c[1] = d.y; c[2] = d.z; c[3] = d.w;
        }
    } else {
#pragma unroll
        for (int i = 0; i < 4; i++) {
            int e = min(e0 + i, E - 1);
            if (is64) {
                r[i] = (int)((const long long*)ei_raw)[e];
                c[i] = (int)((const long long*)ei_raw)[(size_t)E + e];
            } else {
                r[i] = ((const int*)ei_raw)[e];
                c[i] = ((const int*)ei_raw)[(size_t)E + e];
            }
        }
    }

    float s0, s1, s2, s3;
    {   // edges 0,1 (4 gathers in flight)
        const uint4 p0 = __ldg(reinterpret_cast<const uint4*>(g_PQh + (size_t)r[0] * 128 + sub * 8));
        const uint4 q0 = __ldg(reinterpret_cast<const uint4*>(g_PQh + (size_t)c[0] * 128 + 64 + sub * 8));
        const uint4 p1 = __ldg(reinterpret_cast<const uint4*>(g_PQh + (size_t)r[1] * 128 + sub * 8));
        const uint4 q1 = __ldg(reinterpret_cast<const uint4*>(g_PQh + (size_t)c[1] * 128 + 64 + sub * 8));
        s0 = edge_dot(p0, q0, msk);
        s1 = edge_dot(p1, q1, msk);
    }
    {   // edges 2,3
        const uint4 p2 = __ldg(reinterpret_cast<const uint4*>(g_PQh + (size_t)r[2] * 128 + sub * 8));
        const uint4 q2 = __ldg(reinterpret_cast<const uint4*>(g_PQh + (size_t)c[2] * 128 + 64 + sub * 8));
        const uint4 p3 = __ldg(reinterpret_cast<const uint4*>(g_PQh + (size_t)r[3] * 128 + sub * 8));
        const uint4 q3 = __ldg(reinterpret_cast<const uint4*>(g_PQh + (size_t)c[3] * 128 + 64 + sub * 8));
        s2 = edge_dot(p2, q2, msk);
        s3 = edge_dot(p3, q3, msk);
    }

    s0 += __shfl_down_sync(0xffffffffu, s0, 4, 8);
    s1 += __shfl_down_sync(0xffffffffu, s1, 4, 8);
    s2 += __shfl_down_sync(0xffffffffu, s2, 4, 8);
    s3 += __shfl_down_sync(0xffffffffu, s3, 4, 8);
    s0 += __shfl_down_sync(0xffffffffu, s0, 2, 8);
    s1 += __shfl_down_sync(0xffffffffu, s1, 2, 8);
    s2 += __shfl_down_sync(0xffffffffu, s2, 2, 8);
    s3 += __shfl_down_sync(0xffffffffu, s3, 2, 8);
    s0 += __shfl_down_sync(0xffffffffu, s0, 1, 8);
    s1 += __shfl_down_sync(0xffffffffu, s1, 1, 8);
    s2 += __shfl_down_sync(0xffffffffu, s2, 1, 8);
    s3 += __shfl_down_sync(0xffffffffu, s3, 1, 8);

    if (sub == 0) {
        const float bias = __ldg(b2);
        if (full) {
            float4 o = make_float4(s0 + bias, s1 + bias, s2 + bias, s3 + bias);
            *reinterpret_cast<float4*>(out + e0) = o;   // 16B aligned
        } else {
            float sv[4] = {s0, s1, s2, s3};
#pragma unroll
            for (int i = 0; i < 4; i++)
                if (e0 + i < E) out[e0 + i] = sv[i] + bias;
        }
    }
}

// ---------------------------------------------------------------------------
extern "C" void kernel_launch(void* const* d_in, const int* in_sizes, int n_in,
                              void* d_out, int out_size) {
    const float* z  = (const float*)d_in[0];   // [N, 64]
    const void*  ei = d_in[1];                 // [2, E] int64 or int32
    const float* W1 = (const float*)d_in[2];   // [128, 64]
    const float* b1 = (const float*)d_in[3];   // [64]
    const float* W2 = (const float*)d_in[4];   // [64, 1]
    const float* b2 = (const float*)d_in[5];   // [1]
    float* out = (float*)d_out;                // [E, 1]

    const int M = in_sizes[0] / HIDDEN;        // 100000 nodes
    const int E = in_sizes[1] / 2;             // 3200000 edges

    int n_check = E < 2048 ? E : 2048;
    int gemm_blocks = (M + 128 * TILES - 1) / (128 * TILES);
    node_gemm_kernel<<<gemm_blocks, 256>>>(z, W1, b1, W2,
                                           (const long long*)ei, n_check, M);

    const int nslots = (E + 3) / 4;
    long long total_threads = (long long)nslots * 8;
    int edge_blocks = (int)((total_threads + 255) / 256);
    edge_kernel<<<edge_blocks, 256>>>(ei, b2, out, E, nslots);
}

// round 11
// speedup vs baseline: 1.3229x; 1.0592x over previous
#include <cuda_runtime.h>
#include <cuda_fp16.h>
#include <cstdint>

// EdgeDecoder:
//   out[e] = relu(P[row]+Q[col]) . W2 + b2
// |W2| folded into PQ at GEMM epilogue; edge pass applies signs by XORing
// the fp16 sign bit post-relu, then a two-level hadd2 tree before fp32.
// Phase 1: tensor-core node GEMM (mma.m16n8k16), grid-stride tiles over
//          304 blocks (one full wave at occ 2) for load balance.
// Phase 2: edge pass, 8 lanes/edge, 4 consecutive edges per lane-slot.

#define HIDDEN 64
#define NMAX   100000

__device__ __half    g_PQh[(size_t)NMAX * 128];  // [node][0:64]=P', [64:128]=Q'
__device__ int       g_idx_is64;
__device__ uint32_t  g_sign[2];                  // bit j = 1 if W2[j] < 0

// ---------------------------------------------------------------------------
__device__ __forceinline__ void mma16816(float* c,
                                         uint32_t a0, uint32_t a1,
                                         uint32_t a2, uint32_t a3,
                                         uint32_t b0, uint32_t b1) {
    asm volatile(
        "mma.sync.aligned.m16n8k16.row.col.f32.f16.f16.f32 "
        "{%0,%1,%2,%3}, {%4,%5,%6,%7}, {%8,%9}, {%0,%1,%2,%3};"
        : "+f"(c[0]), "+f"(c[1]), "+f"(c[2]), "+f"(c[3])
        : "r"(a0), "r"(a1), "r"(a2), "r"(a3), "r"(b0), "r"(b1));
}

// ---------------------------------------------------------------------------
// Node GEMM: PQ[M,128] = fp16( (z[M,64] @ Wcat[64,128] + bias) * |W2| )
// Grid-stride over 128-row tiles; W^T fp16 prepared once per block.
// ---------------------------------------------------------------------------
#define ZROW 72
#define SROW 136
#define GEMM_GRID 304   // 2 blocks x 152 SMs = one full wave at occ 2

__global__ void __launch_bounds__(256, 2)
node_gemm_kernel(const float* __restrict__ z,
                 const float* __restrict__ W1,
                 const float* __restrict__ b1,
                 const float* __restrict__ W2,
                 const long long* __restrict__ ei,
                 int n_check, int M) {
    __shared__ __half zh[128 * ZROW];     // 18 KB; reused as 64-row stage
    __shared__ __half wt[128 * ZROW];     // 18 KB; W^T: wt[c][k]
    __shared__ float  scale_s[128];
    __shared__ float  bias_s[128];

    const int tid  = threadIdx.x;
    const int lane = tid & 31;
    const int warp = tid >> 5;

    if (blockIdx.x == 0) {
        if (tid < 64) {
            unsigned m = __ballot_sync(0xffffffffu, W2[tid] < 0.f);
            if ((tid & 31) == 0) g_sign[tid >> 5] = m;
        }
        __shared__ int bad;
        if (tid == 0) bad = 0;
        __syncthreads();
        for (int i = tid; i < n_check; i += blockDim.x) {
            long long v = ei[i];
            if (v < 0 || v >= (long long)M) bad = 1;   // benign race
        }
        __syncthreads();
        if (tid == 0) g_idx_is64 = bad ? 0 : 1;
    }

    if (tid < 128) {
        int j = tid & 63;
        scale_s[tid] = fabsf(__ldg(W2 + j));
        bias_s[tid]  = (tid < 64) ? __ldg(b1 + tid) : 0.f;
    }

    for (int i = tid; i < 128 * 64; i += 256) {
        int kp = i >> 6;
        int j  = i & 63;
        int c  = (kp < 64) ? j : (j + 64);
        int k  = (kp < 64) ? kp : (kp - 64);
        wt[c * ZROW + k] = __float2half(W1[i]);
    }

    const int g  = lane >> 2;
    const int tg = lane & 3;
    const int mrow = warp * 16;
    const int ntiles = (M + 127) / 128;

    for (int tile = blockIdx.x; tile < ntiles; tile += gridDim.x) {
        const int row0 = tile * 128;

        __syncthreads();   // W/stage quiescent; safe to (re)fill zh

        for (int i = tid; i < 128 * 16; i += 256) {
            int r  = i >> 4;
            int c4 = i & 15;
            float4 v = make_float4(0.f, 0.f, 0.f, 0.f);
            if (row0 + r < M)
                v = *reinterpret_cast<const float4*>(z + (size_t)(row0 + r) * 64 + c4 * 4);
            __half2 h0 = __floats2half2_rn(v.x, v.y);
            __half2 h1 = __floats2half2_rn(v.z, v.w);
            *reinterpret_cast<__half2*>(&zh[r * ZROW + c4 * 4])     = h0;
            *reinterpret_cast<__half2*>(&zh[r * ZROW + c4 * 4 + 2]) = h1;
        }
        __syncthreads();

        float acc[16][4];
#pragma unroll
        for (int t = 0; t < 16; t++)
#pragma unroll
            for (int i = 0; i < 4; i++) acc[t][i] = 0.f;

#pragma unroll
        for (int ks = 0; ks < 4; ks++) {
            const int kb = ks * 16 + 2 * tg;
            uint32_t a0 = *reinterpret_cast<const uint32_t*>(&zh[(mrow + g) * ZROW + kb]);
            uint32_t a1 = *reinterpret_cast<const uint32_t*>(&zh[(mrow + g + 8) * ZROW + kb]);
            uint32_t a2 = *reinterpret_cast<const uint32_t*>(&zh[(mrow + g) * ZROW + kb + 8]);
            uint32_t a3 = *reinterpret_cast<const uint32_t*>(&zh[(mrow + g + 8) * ZROW + kb + 8]);
#pragma unroll
            for (int t = 0; t < 16; t++) {
                uint32_t b0  = *reinterpret_cast<const uint32_t*>(&wt[(t * 8 + g) * ZROW + kb]);
                uint32_t b1r = *reinterpret_cast<const uint32_t*>(&wt[(t * 8 + g) * ZROW + kb + 8]);
                mma16816(acc[t], a0, a1, a2, a3, b0, b1r);
            }
        }

        __half* stage = zh;
#pragma unroll
        for (int pass = 0; pass < 2; pass++) {
            __syncthreads();
            if ((warp >> 2) == pass) {
                const int srow = mrow - pass * 64;
#pragma unroll
                for (int t = 0; t < 16; t++) {
                    int n = t * 8 + 2 * tg;
                    float s0 = scale_s[n], s1 = scale_s[n + 1];
                    float bb0 = bias_s[n], bb1 = bias_s[n + 1];
                    __half2 h0 = __floats2half2_rn((acc[t][0] + bb0) * s0,
                                                   (acc[t][1] + bb1) * s1);
                    __half2 h1 = __floats2half2_rn((acc[t][2] + bb0) * s0,
                                                   (acc[t][3] + bb1) * s1);
                    *reinterpret_cast<__half2*>(&stage[(srow + g) * SROW + n])     = h0;
                    *reinterpret_cast<__half2*>(&stage[(srow + g + 8) * SROW + n]) = h1;
                }
            }
            __syncthreads();
#pragma unroll
            for (int i = 0; i < 4; i++) {
                int idx = tid + i * 256;
                int r   = idx >> 4;
                int c16 = idx & 15;
                int grow = row0 + pass * 64 + r;
                if (grow < M) {
                    uint4 v = *reinterpret_cast<const uint4*>(&stage[r * SROW + c16 * 8]);
                    *reinterpret_cast<uint4*>(&g_PQh[(size_t)grow * 128 + c16 * 8]) = v;
                }
            }
        }
    }
}

// ---------------------------------------------------------------------------
// Edge pass: 8 lanes/edge, 4 consecutive edges per slot.
// Two-level fp16 add tree, single cvt at the end.
// ---------------------------------------------------------------------------
__device__ __forceinline__ float edge_dot(const uint4& pv, const uint4& qv,
                                          const uint32_t* msk) {
    const __half2* ph = reinterpret_cast<const __half2*>(&pv);
    const __half2* qh = reinterpret_cast<const __half2*>(&qv);
    const __half2 zero = __float2half2_rn(0.f);
    __half2 hs[4];
#pragma unroll
    for (int i = 0; i < 4; i++) {
        __half2 h = __hmax2(__hadd2(ph[i], qh[i]), zero);
        uint32_t u = *reinterpret_cast<uint32_t*>(&h) ^ msk[i];
        hs[i] = *reinterpret_cast<__half2*>(&u);
    }
    __half2 t0 = __hadd2(hs[0], hs[1]);
    __half2 t1 = __hadd2(hs[2], hs[3]);
    __half2 t  = __hadd2(t0, t1);        // two fp16 add levels
    float2 f = __half22float2(t);
    return f.x + f.y;
}

__global__ void __launch_bounds__(256)
edge_kernel(const void* __restrict__ ei_raw,
            const float* __restrict__ b2,
            float* __restrict__ out,
            int E, int nslots) {
    const int t = blockIdx.x * blockDim.x + threadIdx.x;
    const int slot = t >> 3;
    if (slot >= nslots) return;
    const int sub = t & 7;
    const int e0 = slot * 4;

    const uint32_t bits = g_sign[sub >> 2];
    const uint32_t b8 = (bits >> ((sub & 3) * 8)) & 0xFFu;
    uint32_t msk[4];
#pragma unroll
    for (int i = 0; i < 4; i++)
        msk[i] = (((b8 >> (2 * i)) & 1u) << 15) |
                 (((b8 >> (2 * i + 1)) & 1u) << 31);

    const bool is64 = (g_idx_is64 != 0);
    const bool full = ((E & 3) == 0);

    int r[4], c[4];
    if (full) {
        if (is64) {
            const longlong2* pr = reinterpret_cast<const longlong2*>(
                (const long long*)ei_raw + e0);
            longlong2 a = __ldg(pr), b = __ldg(pr + 1);
            r[0] = (int)a.x; r[1] = (int)a.y; r[2] = (int)b.x; r[3] = (int)b.y;
            const longlong2* pc = reinterpret_cast<const longlong2*>(
                (const long long*)ei_raw + (size_t)E + e0);
            longlong2 d = __ldg(pc), f = __ldg(pc + 1);
            c[0] = (int)d.x; c[1] = (int)d.y; c[2] = (int)f.x; c[3] = (int)f.y;
        } else {
            int4 a = __ldg(reinterpret_cast<const int4*>((const int*)ei_raw + e0));
            r[0] = a.x; r[1] = a.y; r[2] = a.z; r[3] = a.w;
            int4 d = __ldg(reinterpret_cast<const int4*>(
                (const int*)ei_raw + (size_t)E + e0));
            c[0] = d.x; c[1] = d.y; c[2] = d.z; c[3] = d.w;
        }
    } else {
#pragma unroll
        for (int i = 0; i < 4; i++) {
            int e = min(e0 + i, E - 1);
            if (is64) {
                r[i] = (int)((const long long*)ei_raw)[e];
                c[i] = (int)((const long long*)ei_raw)[(size_t)E + e];
            } else {
                r[i] = ((const int*)ei_raw)[e];
                c[i] = ((const int*)ei_raw)[(size_t)E + e];
            }
        }
    }

    float s0, s1, s2, s3;
    {
        const uint4 p0 = __ldg(reinterpret_cast<const uint4*>(g_PQh + (size_t)r[0] * 128 + sub * 8));
        const uint4 q0 = __ldg(reinterpret_cast<const uint4*>(g_PQh + (size_t)c[0] * 128 + 64 + sub * 8));
        const uint4 p1 = __ldg(reinterpret_cast<const uint4*>(g_PQh + (size_t)r[1] * 128 + sub * 8));
        const uint4 q1 = __ldg(reinterpret_cast<const uint4*>(g_PQh + (size_t)c[1] * 128 + 64 + sub * 8));
        s0 = edge_dot(p0, q0, msk);
        s1 = edge_dot(p1, q1, msk);
    }
    {
        const uint4 p2 = __ldg(reinterpret_cast<const uint4*>(g_PQh + (size_t)r[2] * 128 + sub * 8));
        const uint4 q2 = __ldg(reinterpret_cast<const uint4*>(g_PQh + (size_t)c[2] * 128 + 64 + sub * 8));
        const uint4 p3 = __ldg(reinterpret_cast<const uint4*>(g_PQh + (size_t)r[3] * 128 + sub * 8));
        const uint4 q3 = __ldg(reinterpret_cast<const uint4*>(g_PQh + (size_t)c[3] * 128 + 64 + sub * 8));
        s2 = edge_dot(p2, q2, msk);
        s3 = edge_dot(p3, q3, msk);
    }

    s0 += __shfl_down_sync(0xffffffffu, s0, 4, 8);
    s1 += __shfl_down_sync(0xffffffffu, s1, 4, 8);
    s2 += __shfl_down_sync(0xffffffffu, s2, 4, 8);
    s3 += __shfl_down_sync(0xffffffffu, s3, 4, 8);
    s0 += __shfl_down_sync(0xffffffffu, s0, 2, 8);
    s1 += __shfl_down_sync(0xffffffffu, s1, 2, 8);
    s2 += __shfl_down_sync(0xffffffffu, s2, 2, 8);
    s3 += __shfl_down_sync(0xffffffffu, s3, 2, 8);
    s0 += __shfl_down_sync(0xffffffffu, s0, 1, 8);
    s1 += __shfl_down_sync(0xffffffffu, s1, 1, 8);
    s2 += __shfl_down_sync(0xffffffffu, s2, 1, 8);
    s3 += __shfl_down_sync(0xffffffffu, s3, 1, 8);

    if (sub == 0) {
        const float bias = __ldg(b2);
        if (full) {
            float4 o = make_float4(s0 + bias, s1 + bias, s2 + bias, s3 + bias);
            *reinterpret_cast<float4*>(out + e0) = o;
        } else {
            float sv[4] = {s0, s1, s2, s3};
#pragma unroll
            for (int i = 0; i < 4; i++)
                if (e0 + i < E) out[e0 + i] = sv[i] + bias;
        }
    }
}

// ---------------------------------------------------------------------------
extern "C" void kernel_launch(void* const* d_in, const int* in_sizes, int n_in,
                              void* d_out, int out_size) {
    const float* z  = (const float*)d_in[0];   // [N, 64]
    const void*  ei = d_in[1];                 // [2, E] int64 or int32
    const float* W1 = (const float*)d_in[2];   // [128, 64]
    const float* b1 = (const float*)d_in[3];   // [64]
    const float* W2 = (const float*)d_in[4];   // [64, 1]
    const float* b2 = (const float*)d_in[5];   // [1]
    float* out = (float*)d_out;                // [E, 1]

    const int M = in_sizes[0] / HIDDEN;        // 100000 nodes
    const int E = in_sizes[1] / 2;             // 3200000 edges

    int n_check = E < 2048 ? E : 2048;
    int ntiles = (M + 127) / 128;
    int gemm_blocks = ntiles < GEMM_GRID ? ntiles : GEMM_GRID;
    node_gemm_kernel<<<gemm_blocks, 256>>>(z, W1, b1, W2,
                                           (const long long*)ei, n_check, M);

    const int nslots = (E + 3) / 4;
    long long total_threads = (long long)nslots * 8;
    int edge_blocks = (int)((total_threads + 255) / 256);
    edge_kernel<<<edge_blocks, 256>>>(ei, b2, out, E, nslots);
}

// round 12
// speedup vs baseline: 1.3868x; 1.0483x over previous
#include <cuda_runtime.h>
#include <cuda_fp16.h>
#include <cstdint>

// EdgeDecoder:
//   out[e] = relu(P[row]+Q[col]) . W2 + b2
// |W2| folded into PQ at GEMM epilogue; edge pass applies signs by XORing
// the fp16 sign bit post-relu, two-level hadd2 tree, then a 5-shuffle
// value-folding butterfly reduction (4 edge sums over 8 lanes).
// Phase 1: tensor-core node GEMM (mma.m16n8k16), grid-stride over 304 blocks.
// Phase 2: edge pass, 8 lanes/edge, 4 consecutive edges per lane-slot.

#define HIDDEN 64
#define NMAX   100000

__device__ __half    g_PQh[(size_t)NMAX * 128];  // [node][0:64]=P', [64:128]=Q'
__device__ int       g_idx_is64;
__device__ uint32_t  g_sign[2];                  // bit j = 1 if W2[j] < 0

// ---------------------------------------------------------------------------
__device__ __forceinline__ void mma16816(float* c,
                                         uint32_t a0, uint32_t a1,
                                         uint32_t a2, uint32_t a3,
                                         uint32_t b0, uint32_t b1) {
    asm volatile(
        "mma.sync.aligned.m16n8k16.row.col.f32.f16.f16.f32 "
        "{%0,%1,%2,%3}, {%4,%5,%6,%7}, {%8,%9}, {%0,%1,%2,%3};"
        : "+f"(c[0]), "+f"(c[1]), "+f"(c[2]), "+f"(c[3])
        : "r"(a0), "r"(a1), "r"(a2), "r"(a3), "r"(b0), "r"(b1));
}

// ---------------------------------------------------------------------------
// Node GEMM: PQ[M,128] = fp16( (z[M,64] @ Wcat[64,128] + bias) * |W2| )
// Grid-stride over 128-row tiles; W^T fp16 prepared once per block.
// ---------------------------------------------------------------------------
#define ZROW 72
#define SROW 136
#define GEMM_GRID 304

__global__ void __launch_bounds__(256, 2)
node_gemm_kernel(const float* __restrict__ z,
                 const float* __restrict__ W1,
                 const float* __restrict__ b1,
                 const float* __restrict__ W2,
                 const long long* __restrict__ ei,
                 int n_check, int M) {
    __shared__ __half zh[128 * ZROW];     // 18 KB; reused as 64-row stage
    __shared__ __half wt[128 * ZROW];     // 18 KB; W^T: wt[c][k]
    __shared__ float  scale_s[128];
    __shared__ float  bias_s[128];

    const int tid  = threadIdx.x;
    const int lane = tid & 31;
    const int warp = tid >> 5;

    if (blockIdx.x == 0) {
        if (tid < 64) {
            unsigned m = __ballot_sync(0xffffffffu, W2[tid] < 0.f);
            if ((tid & 31) == 0) g_sign[tid >> 5] = m;
        }
        __shared__ int bad;
        if (tid == 0) bad = 0;
        __syncthreads();
        for (int i = tid; i < n_check; i += blockDim.x) {
            long long v = ei[i];
            if (v < 0 || v >= (long long)M) bad = 1;   // benign race
        }
        __syncthreads();
        if (tid == 0) g_idx_is64 = bad ? 0 : 1;
    }

    if (tid < 128) {
        int j = tid & 63;
        scale_s[tid] = fabsf(__ldg(W2 + j));
        bias_s[tid]  = (tid < 64) ? __ldg(b1 + tid) : 0.f;
    }

    for (int i = tid; i < 128 * 64; i += 256) {
        int kp = i >> 6;
        int j  = i & 63;
        int c  = (kp < 64) ? j : (j + 64);
        int k  = (kp < 64) ? kp : (kp - 64);
        wt[c * ZROW + k] = __float2half(W1[i]);
    }

    const int g  = lane >> 2;
    const int tg = lane & 3;
    const int mrow = warp * 16;
    const int ntiles = (M + 127) / 128;

    for (int tile = blockIdx.x; tile < ntiles; tile += gridDim.x) {
        const int row0 = tile * 128;

        __syncthreads();

        for (int i = tid; i < 128 * 16; i += 256) {
            int r  = i >> 4;
            int c4 = i & 15;
            float4 v = make_float4(0.f, 0.f, 0.f, 0.f);
            if (row0 + r < M)
                v = *reinterpret_cast<const float4*>(z + (size_t)(row0 + r) * 64 + c4 * 4);
            __half2 h0 = __floats2half2_rn(v.x, v.y);
            __half2 h1 = __floats2half2_rn(v.z, v.w);
            *reinterpret_cast<__half2*>(&zh[r * ZROW + c4 * 4])     = h0;
            *reinterpret_cast<__half2*>(&zh[r * ZROW + c4 * 4 + 2]) = h1;
        }
        __syncthreads();

        float acc[16][4];
#pragma unroll
        for (int t = 0; t < 16; t++)
#pragma unroll
            for (int i = 0; i < 4; i++) acc[t][i] = 0.f;

#pragma unroll
        for (int ks = 0; ks < 4; ks++) {
            const int kb = ks * 16 + 2 * tg;
            uint32_t a0 = *reinterpret_cast<const uint32_t*>(&zh[(mrow + g) * ZROW + kb]);
            uint32_t a1 = *reinterpret_cast<const uint32_t*>(&zh[(mrow + g + 8) * ZROW + kb]);
            uint32_t a2 = *reinterpret_cast<const uint32_t*>(&zh[(mrow + g) * ZROW + kb + 8]);
            uint32_t a3 = *reinterpret_cast<const uint32_t*>(&zh[(mrow + g + 8) * ZROW + kb + 8]);
#pragma unroll
            for (int t = 0; t < 16; t++) {
                uint32_t b0  = *reinterpret_cast<const uint32_t*>(&wt[(t * 8 + g) * ZROW + kb]);
                uint32_t b1r = *reinterpret_cast<const uint32_t*>(&wt[(t * 8 + g) * ZROW + kb + 8]);
                mma16816(acc[t], a0, a1, a2, a3, b0, b1r);
            }
        }

        __half* stage = zh;
#pragma unroll
        for (int pass = 0; pass < 2; pass++) {
            __syncthreads();
            if ((warp >> 2) == pass) {
                const int srow = mrow - pass * 64;
#pragma unroll
                for (int t = 0; t < 16; t++) {
                    int n = t * 8 + 2 * tg;
                    float s0 = scale_s[n], s1 = scale_s[n + 1];
                    float bb0 = bias_s[n], bb1 = bias_s[n + 1];
                    __half2 h0 = __floats2half2_rn((acc[t][0] + bb0) * s0,
                                                   (acc[t][1] + bb1) * s1);
                    __half2 h1 = __floats2half2_rn((acc[t][2] + bb0) * s0,
                                                   (acc[t][3] + bb1) * s1);
                    *reinterpret_cast<__half2*>(&stage[(srow + g) * SROW + n])     = h0;
                    *reinterpret_cast<__half2*>(&stage[(srow + g + 8) * SROW + n]) = h1;
                }
            }
            __syncthreads();
#pragma unroll
            for (int i = 0; i < 4; i++) {
                int idx = tid + i * 256;
                int r   = idx >> 4;
                int c16 = idx & 15;
                int grow = row0 + pass * 64 + r;
                if (grow < M) {
                    uint4 v = *reinterpret_cast<const uint4*>(&stage[r * SROW + c16 * 8]);
                    *reinterpret_cast<uint4*>(&g_PQh[(size_t)grow * 128 + c16 * 8]) = v;
                }
            }
        }
    }
}

// ---------------------------------------------------------------------------
// Edge pass: 8 lanes/edge, 4 consecutive edges per slot.
// ---------------------------------------------------------------------------
__device__ __forceinline__ float edge_dot(const uint4& pv, const uint4& qv,
                                          const uint32_t* msk) {
    const __half2* ph = reinterpret_cast<const __half2*>(&pv);
    const __half2* qh = reinterpret_cast<const __half2*>(&qv);
    const __half2 zero = __float2half2_rn(0.f);
    __half2 hs[4];
#pragma unroll
    for (int i = 0; i < 4; i++) {
        __half2 h = __hmax2(__hadd2(ph[i], qh[i]), zero);
        uint32_t u = *reinterpret_cast<uint32_t*>(&h) ^ msk[i];
        hs[i] = *reinterpret_cast<__half2*>(&u);
    }
    __half2 t0 = __hadd2(hs[0], hs[1]);
    __half2 t1 = __hadd2(hs[2], hs[3]);
    __half2 t  = __hadd2(t0, t1);
    float2 f = __half22float2(t);
    return f.x + f.y;
}

__global__ void __launch_bounds__(256)
edge_kernel(const void* __restrict__ ei_raw,
            const float* __restrict__ b2,
            float* __restrict__ out,
            int E, int nslots) {
    const int t = blockIdx.x * blockDim.x + threadIdx.x;
    const int slot = t >> 3;
    if (slot >= nslots) return;
    const int sub = t & 7;
    const int e0 = slot * 4;

    const uint32_t bits = g_sign[sub >> 2];
    const uint32_t b8 = (bits >> ((sub & 3) * 8)) & 0xFFu;
    uint32_t msk[4];
#pragma unroll
    for (int i = 0; i < 4; i++)
        msk[i] = (((b8 >> (2 * i)) & 1u) << 15) |
                 (((b8 >> (2 * i + 1)) & 1u) << 31);

    const bool is64 = (g_idx_is64 != 0);
    const bool full = ((E & 3) == 0);

    int r[4], c[4];
    if (full) {
        if (is64) {
            const longlong2* pr = reinterpret_cast<const longlong2*>(
                (const long long*)ei_raw + e0);
            longlong2 a = __ldg(pr), b = __ldg(pr + 1);
            r[0] = (int)a.x; r[1] = (int)a.y; r[2] = (int)b.x; r[3] = (int)b.y;
            const longlong2* pc = reinterpret_cast<const longlong2*>(
                (const long long*)ei_raw + (size_t)E + e0);
            longlong2 d = __ldg(pc), f = __ldg(pc + 1);
            c[0] = (int)d.x; c[1] = (int)d.y; c[2] = (int)f.x; c[3] = (int)f.y;
        } else {
            int4 a = __ldg(reinterpret_cast<const int4*>((const int*)ei_raw + e0));
            r[0] = a.x; r[1] = a.y; r[2] = a.z; r[3] = a.w;
            int4 d = __ldg(reinterpret_cast<const int4*>(
                (const int*)ei_raw + (size_t)E + e0));
            c[0] = d.x; c[1] = d.y; c[2] = d.z; c[3] = d.w;
        }
    } else {
#pragma unroll
        for (int i = 0; i < 4; i++) {
            int e = min(e0 + i, E - 1);
            if (is64) {
                r[i] = (int)((const long long*)ei_raw)[e];
                c[i] = (int)((const long long*)ei_raw)[(size_t)E + e];
            } else {
                r[i] = ((const int*)ei_raw)[e];
                c[i] = ((const int*)ei_raw)[(size_t)E + e];
            }
        }
    }

    float s0, s1, s2, s3;
    {
        const uint4 p0 = __ldg(reinterpret_cast<const uint4*>(g_PQh + (size_t)r[0] * 128 + sub * 8));
        const uint4 q0 = __ldg(reinterpret_cast<const uint4*>(g_PQh + (size_t)c[0] * 128 + 64 + sub * 8));
        const uint4 p1 = __ldg(reinterpret_cast<const uint4*>(g_PQh + (size_t)r[1] * 128 + sub * 8));
        const uint4 q1 = __ldg(reinterpret_cast<const uint4*>(g_PQh + (size_t)c[1] * 128 + 64 + sub * 8));
        s0 = edge_dot(p0, q0, msk);
        s1 = edge_dot(p1, q1, msk);
    }
    {
        const uint4 p2 = __ldg(reinterpret_cast<const uint4*>(g_PQh + (size_t)r[2] * 128 + sub * 8));
        const uint4 q2 = __ldg(reinterpret_cast<const uint4*>(g_PQh + (size_t)c[2] * 128 + 64 + sub * 8));
        const uint4 p3 = __ldg(reinterpret_cast<const uint4*>(g_PQh + (size_t)r[3] * 128 + sub * 8));
        const uint4 q3 = __ldg(reinterpret_cast<const uint4*>(g_PQh + (size_t)c[3] * 128 + 64 + sub * 8));
        s2 = edge_dot(p2, q2, msk);
        s3 = edge_dot(p3, q3, msk);
    }

    // ---- 5-shuffle value-folding butterfly over the 8-lane group ----
    // After xor4: low half carries (s0,s1) partials, high half (s2,s3).
    const bool hi = (sub & 4) != 0;
    float xa = hi ? s0 : s2;                       // send what partner needs
    float ra = __shfl_xor_sync(0xffffffffu, xa, 4, 8);
    float a  = (hi ? s2 : s0) + ra;                // lanes<4: v0-chain; >=4: v2
    float xb = hi ? s1 : s3;
    float rb = __shfl_xor_sync(0xffffffffu, xb, 4, 8);
    float b  = (hi ? s3 : s1) + rb;                // lanes<4: v1-chain; >=4: v3

    a += __shfl_xor_sync(0xffffffffu, a, 2, 8);
    b += __shfl_xor_sync(0xffffffffu, b, 2, 8);

    const bool odd = (sub & 1) != 0;
    float xc = odd ? a : b;
    float rc = __shfl_xor_sync(0xffffffffu, xc, 1, 8);
    float res = (odd ? b : a) + rc;
    // lane 0: sum(s0), lane 1: sum(s1), lane 4: sum(s2), lane 5: sum(s3)

    if ((sub & 2) == 0) {                          // lanes 0,1,4,5
        const int pos = (sub & 1) | ((sub >> 1) & 2);   // 0,1,2,3
        const int e = e0 + pos;
        if (e < E) out[e] = res + __ldg(b2);
    }
}

// ---------------------------------------------------------------------------
extern "C" void kernel_launch(void* const* d_in, const int* in_sizes, int n_in,
                              void* d_out, int out_size) {
    const float* z  = (const float*)d_in[0];   // [N, 64]
    const void*  ei = d_in[1];                 // [2, E] int64 or int32
    const float* W1 = (const float*)d_in[2];   // [128, 64]
    const float* b1 = (const float*)d_in[3];   // [64]
    const float* W2 = (const float*)d_in[4];   // [64, 1]
    const float* b2 = (const float*)d_in[5];   // [1]
    float* out = (float*)d_out;                // [E, 1]

    const int M = in_sizes[0] / HIDDEN;        // 100000 nodes
    const int E = in_sizes[1] / 2;             // 3200000 edges

    int n_check = E < 2048 ? E : 2048;
    int ntiles = (M + 127) / 128;
    int gemm_blocks = ntiles < GEMM_GRID ? ntiles : GEMM_GRID;
    node_gemm_kernel<<<gemm_blocks, 256>>>(z, W1, b1, W2,
                                           (const long long*)ei, n_check, M);

    const int nslots = (E + 3) / 4;
    long long total_threads = (long long)nslots * 8;
    int edge_blocks = (int)((total_threads + 255) / 256);
    edge_kernel<<<edge_blocks, 256>>>(ei, b2, out, E, nslots);
}